// round 9
// baseline (speedup 1.0000x reference)
#include <cuda_runtime.h>
#include <cuda_fp16.h>
#include <cstdint>

#define SGRID 1024
#define BSHIFT 12
#define NB (1 << 18)
#define NBLK 256            // scan blocks (NB / 1024)
#define MAXN 400000
#define MAXM (1 << 20)

static __device__ int d_keys[MAXN];
static __device__ int d_cnt[NB];                     // self-restoring: scatter returns it to 0
static __device__ int d_offs[NB + 1];
static __device__ unsigned long long d_look[NBLK];
static __device__ int2 d_bpair[MAXN];                // (key, original idx) in bucket order
static __device__ int d_gidx[MAXN];
static __device__ int d_mi[MAXM];                    // output row r
static __device__ int d_mj[MAXM];
static __device__ int d_mk[MAXM];
static __device__ int d_mcount;
static __device__ __align__(16) __half d_Wh[4096];   // W[13]^T as half: [co][ci]
static __device__ __align__(16) __half d_Fh[(size_t)MAXN * 64];  // features as half

// ---------------- fp32 -> fp16 feature image (overlapped with bucket pipeline) ----------------

__global__ void k_tohalf(const float* __restrict__ F, int n) {
    int i = blockIdx.x * 256 + threadIdx.x;    // 8 floats per thread
    int total = n * 8;                          // n*64/8
    if (i >= total) return;
    const float4* src = (const float4*)F;
    float4 a = src[i * 2], b = src[i * 2 + 1];
    __half2 h0 = __floats2half2_rn(a.x, a.y);
    __half2 h1 = __floats2half2_rn(a.z, a.w);
    __half2 h2 = __floats2half2_rn(b.x, b.y);
    __half2 h3 = __floats2half2_rn(b.z, b.w);
    uint4 o = make_uint4(*(unsigned*)&h0, *(unsigned*)&h1, *(unsigned*)&h2, *(unsigned*)&h3);
    ((uint4*)d_Fh)[i] = o;
}

// ---------------- fused init + keys + histogram ----------------

__global__ void k_keys_hist(const int* __restrict__ coords, const float* __restrict__ W, int n) {
    __shared__ int sc[768];
    int tid = threadIdx.x;
    int t = blockIdx.x * 256 + tid;

    if (t < NBLK) d_look[t] = 0ull;
    if (t == 0) d_mcount = 0;
    if (t < 4096) {
        int co = t >> 6, ci = t & 63;
        d_Wh[t] = __float2half(W[13 * 4096 + ci * 64 + co]);
    }

    int base = blockIdx.x * 768;
#pragma unroll
    for (int x = tid; x < 768; x += 256) {
        int g = base + x;
        if (g < n * 3) sc[x] = coords[g];
    }
    __syncthreads();
    if (t >= n) return;
    int key = (sc[tid * 3] * SGRID + sc[tid * 3 + 1]) * SGRID + sc[tid * 3 + 2];
    d_keys[t] = key;
    atomicAdd(&d_cnt[key >> BSHIFT], 1);
}

// single-pass decoupled-lookback scan: 256 blocks x 1024 threads, co-resident
__global__ void __launch_bounds__(1024) k_scan() {
    __shared__ int sh[1024];
    __shared__ int sh_excl;
    int b = blockIdx.x, tid = threadIdx.x;
    int gid = b * 1024 + tid;
    int v = d_cnt[gid];
    sh[tid] = v;
#pragma unroll
    for (int off = 1; off < 1024; off <<= 1) {
        __syncthreads();
        int t = (tid >= off) ? sh[tid - off] : 0;
        __syncthreads();
        sh[tid] += t;
    }
    __syncthreads();
    if (tid == 0) {
        int agg = sh[1023];
        volatile unsigned long long* look = (volatile unsigned long long*)d_look;
        int excl = 0;
        if (b == 0) {
            look[0] = (2ull << 62) | (unsigned)agg;
        } else {
            look[b] = (1ull << 62) | (unsigned)agg;
            int j = b - 1;
            for (;;) {
                unsigned long long w = look[j];
                unsigned long long f = w >> 62;
                if (f == 0) continue;
                excl += (int)(w & 0x3FFFFFFFFFFFFFFFull);
                if (f == 2) break;
                j--;
            }
            look[b] = (2ull << 62) | (unsigned)(excl + agg);
        }
        sh_excl = excl;
    }
    __syncthreads();
    int base = sh_excl;
    d_offs[gid] = base + sh[tid] - v;
    if (gid == NB - 1) d_offs[NB] = base + sh[1023];
}

// 2 points per thread: doubled MLP on the latency-bound atomic path
__global__ void k_scatter(int n) {
    int i0 = (blockIdx.x * blockDim.x + threadIdx.x) * 2;
#pragma unroll
    for (int u = 0; u < 2; u++) {
        int i = i0 + u;
        if (i >= n) return;
        int key = d_keys[i];
        int b = key >> BSHIFT;
        int p = d_offs[b] + atomicSub(&d_cnt[b], 1) - 1;   // restores d_cnt[b] -> 0
        d_bpair[p] = make_int2(key, i);
    }
}

// ---------------- fused rank + probe, sorted-position order (warp-coherent) ----------------

__global__ void __launch_bounds__(256) k_proberank(int n) {
    int p = blockIdx.x * blockDim.x + threadIdx.x;
    if (p >= n) return;
    int2 self = d_bpair[p];
    int key = self.x;
    int b = key >> BSHIFT;

    int s0 = d_offs[b], e0 = d_offs[b + 1];
    int cnt = 0;
    for (int u = s0; u < e0; u++) cnt += (d_bpair[u].x < key);
    int r = s0 + cnt;
    d_gidx[r] = self.y;

    int q[9], s[9], e[9];
#pragma unroll
    for (int g = 0; g < 9; g++) {
        int dq = (g / 3 - 1) * (SGRID * SGRID) + (g % 3 - 1) * SGRID;
        q[g] = key + dq;
        s[g] = d_offs[(q[g] - 1) >> BSHIFT];
        e[g] = d_offs[((q[g] + 1) >> BSHIFT) + 1];
    }

#pragma unroll
    for (int g = 0; g < 9; g++) {
        for (int u = s[g]; u < e[g]; u++) {
            int2 kv = d_bpair[u];
            int d = kv.x - q[g];
            if (d < -1 || d > 1) continue;
            if (d == 0 && g == 4) continue;
            int pos = atomicAdd(&d_mcount, 1);
            if (pos < MAXM) {
                d_mi[pos] = r;
                d_mj[pos] = kv.y;
                d_mk[pos] = g * 3 + d + 1;
            }
        }
    }
}

// ---------------- dense gathered GEMM: fp16 mma.m16n8k16, M=128 x N=64, K=64 ----------------

#define FHP 88   // halves; 176B rows (16B-aligned), 12g mod 32 distinct -> conflict-free
#define WHP 72

__global__ void __launch_bounds__(128, 5) k_gemm_tc(float* __restrict__ out, int n) {
    __shared__ __align__(16) __half Ws[64 * WHP];
    __shared__ __align__(16) __half Fs[128 * FHP];
    int tid = threadIdx.x, lane = tid & 31, warp = tid >> 5;

#pragma unroll
    for (int k = 0; k < 8; k++) {
        int x = tid + 128 * k;
        int r = x >> 4, c = x & 15;
        uint2 v = ((const uint2*)d_Wh)[x];
        *(uint2*)&Ws[r * WHP + c * 4] = v;
    }

    int row0 = blockIdx.x * 128;
    {
        int gr = row0 + tid;
        int gi = d_gidx[(gr < n) ? gr : 0];
        const uint4* src = (const uint4*)(d_Fh + (size_t)gi * 64);
#pragma unroll
        for (int c = 0; c < 8; c++)
            *(uint4*)&Fs[tid * FHP + c * 8] = src[c];
    }
    __syncthreads();

    int g = lane >> 2, t = lane & 3;
    int mBase = warp * 32;
    float acc[2][8][4];
#pragma unroll
    for (int mt = 0; mt < 2; mt++)
#pragma unroll
        for (int nt = 0; nt < 8; nt++)
#pragma unroll
            for (int u = 0; u < 4; u++) acc[mt][nt][u] = 0.f;

#pragma unroll
    for (int k0 = 0; k0 < 64; k0 += 16) {
        unsigned a[2][4];
#pragma unroll
        for (int mt = 0; mt < 2; mt++) {
            int r = mBase + mt * 16;
            a[mt][0] = *(const unsigned*)&Fs[(r + g) * FHP + k0 + 2 * t];
            a[mt][1] = *(const unsigned*)&Fs[(r + g + 8) * FHP + k0 + 2 * t];
            a[mt][2] = *(const unsigned*)&Fs[(r + g) * FHP + k0 + 2 * t + 8];
            a[mt][3] = *(const unsigned*)&Fs[(r + g + 8) * FHP + k0 + 2 * t + 8];
        }
#pragma unroll
        for (int nt = 0; nt < 8; nt++) {
            unsigned b0 = *(const unsigned*)&Ws[(nt * 8 + g) * WHP + k0 + 2 * t];
            unsigned b1 = *(const unsigned*)&Ws[(nt * 8 + g) * WHP + k0 + 2 * t + 8];
#pragma unroll
            for (int mt = 0; mt < 2; mt++) {
                asm volatile(
                    "mma.sync.aligned.m16n8k16.row.col.f32.f16.f16.f32 "
                    "{%0,%1,%2,%3},{%4,%5,%6,%7},{%8,%9},{%0,%1,%2,%3};"
                    : "+f"(acc[mt][nt][0]), "+f"(acc[mt][nt][1]),
                      "+f"(acc[mt][nt][2]), "+f"(acc[mt][nt][3])
                    : "r"(a[mt][0]), "r"(a[mt][1]), "r"(a[mt][2]), "r"(a[mt][3]),
                      "r"(b0), "r"(b1));
            }
        }
    }

#pragma unroll
    for (int mt = 0; mt < 2; mt++) {
        int rA = row0 + mBase + mt * 16 + g;
        int rB = rA + 8;
#pragma unroll
        for (int nt = 0; nt < 8; nt++) {
            int c = nt * 8 + 2 * t;
            if (rA < n) *(float2*)&out[(size_t)rA * 64 + c] =
                make_float2(acc[mt][nt][0], acc[mt][nt][1]);
            if (rB < n) *(float2*)&out[(size_t)rB * 64 + c] =
                make_float2(acc[mt][nt][2], acc[mt][nt][3]);
        }
    }
}

// ---------------- apply corrections ----------------

__global__ void k_apply(const float* __restrict__ F, const float* __restrict__ W,
                        float* __restrict__ out) {
    int warp = (blockIdx.x * blockDim.x + threadIdx.x) >> 5;
    int lane = threadIdx.x & 31;
    int nwarps = (gridDim.x * blockDim.x) >> 5;
    int total = d_mcount;
    if (total > MAXM) total = MAXM;
    for (int m = warp; m < total; m += nwarps) {
        int r = d_mi[m], j = d_mj[m], k = d_mk[m];
        float fv0 = F[j * 64 + lane];
        float fv1 = F[j * 64 + 32 + lane];
        const float* Wk = W + k * 64 * 64;
        float a0 = 0.f, a1 = 0.f;
#pragma unroll
        for (int ci = 0; ci < 32; ci++) {
            float f = __shfl_sync(0xffffffffu, fv0, ci);
            a0 += f * Wk[ci * 64 + lane];
            a1 += f * Wk[ci * 64 + 32 + lane];
        }
#pragma unroll
        for (int ci = 0; ci < 32; ci++) {
            float f = __shfl_sync(0xffffffffu, fv1, ci);
            a0 += f * Wk[(ci + 32) * 64 + lane];
            a1 += f * Wk[(ci + 32) * 64 + 32 + lane];
        }
        atomicAdd(&out[r * 64 + lane], a0);
        atomicAdd(&out[r * 64 + 32 + lane], a1);
    }
}

// ---------------- launch ----------------

extern "C" void kernel_launch(void* const* d_in, const int* in_sizes, int n_in,
                              void* d_out, int out_size) {
    const float* F = (const float*)d_in[0];
    const float* W = (const float*)d_in[1];
    const int* coords = (const int*)d_in[2];
    int n = in_sizes[2] / 3;
    if (n > MAXN) n = MAXN;
    float* out = (float*)d_out;

    static cudaStream_t s2 = nullptr;
    static cudaEvent_t e1 = nullptr, e2 = nullptr;
    if (!s2) {
        cudaStreamCreateWithFlags(&s2, cudaStreamNonBlocking);
        cudaEventCreateWithFlags(&e1, cudaEventDisableTiming);
        cudaEventCreateWithFlags(&e2, cudaEventDisableTiming);
    }

    // fork: BW-bound fp16 conversion overlaps the latency-bound bucket pipeline
    cudaEventRecord(e1, 0);
    cudaStreamWaitEvent(s2, e1, 0);
    k_tohalf<<<(n * 8 + 255) / 256, 256, 0, s2>>>(F, n);
    cudaEventRecord(e2, s2);

    k_keys_hist<<<(n + 255) / 256, 256>>>(coords, W, n);
    k_scan<<<NBLK, 1024>>>();
    k_scatter<<<(n + 511) / 512, 256>>>(n);
    k_proberank<<<(n + 255) / 256, 256>>>(n);

    cudaStreamWaitEvent(0, e2, 0);   // join before GEMM reads d_Fh
    k_gemm_tc<<<(n + 127) / 128, 128>>>(out, n);
    k_apply<<<256, 256>>>(F, W, out);
}

// round 10
// speedup vs baseline: 1.2312x; 1.2312x over previous
#include <cuda_runtime.h>
#include <cuda_fp16.h>
#include <cstdint>

#define SGRID 1024
#define BSHIFT 12
#define NB (1 << 18)
#define NBLK 256            // scan blocks (NB / 1024)
#define MAXN 400000
#define MAXM (1 << 20)

static __device__ int d_keys[MAXN];
static __device__ int d_cnt[NB];                     // self-restoring: scatter returns it to 0
static __device__ int d_offs[NB + 1];
static __device__ unsigned long long d_look[NBLK];
static __device__ int2 d_bpair[MAXN];                // (key, original idx) in bucket order
static __device__ int d_rowof[MAXN];                 // original idx -> output row
static __device__ int d_mi[MAXM];                    // output row r
static __device__ int d_mj[MAXM];
static __device__ int d_mk[MAXM];
static __device__ int d_mcount;
static __device__ __align__(16) __half d_Wh[4096];   // W[13]^T as half: [co][ci]

// ---------------- fused init + keys + histogram ----------------

__global__ void k_keys_hist(const int* __restrict__ coords, const float* __restrict__ W, int n) {
    __shared__ int sc[768];
    int tid = threadIdx.x;
    int t = blockIdx.x * 256 + tid;

    if (t < NBLK) d_look[t] = 0ull;
    if (t == 0) d_mcount = 0;
    if (t < 4096) {
        int co = t >> 6, ci = t & 63;
        d_Wh[t] = __float2half(W[13 * 4096 + ci * 64 + co]);
    }

    int base = blockIdx.x * 768;
#pragma unroll
    for (int x = tid; x < 768; x += 256) {
        int g = base + x;
        if (g < n * 3) sc[x] = coords[g];
    }
    __syncthreads();
    if (t >= n) return;
    int key = (sc[tid * 3] * SGRID + sc[tid * 3 + 1]) * SGRID + sc[tid * 3 + 2];
    d_keys[t] = key;
    atomicAdd(&d_cnt[key >> BSHIFT], 1);
}

// single-pass decoupled-lookback scan: 256 blocks x 1024 threads, co-resident
__global__ void __launch_bounds__(1024) k_scan() {
    __shared__ int sh[1024];
    __shared__ int sh_excl;
    int b = blockIdx.x, tid = threadIdx.x;
    int gid = b * 1024 + tid;
    int v = d_cnt[gid];
    sh[tid] = v;
#pragma unroll
    for (int off = 1; off < 1024; off <<= 1) {
        __syncthreads();
        int t = (tid >= off) ? sh[tid - off] : 0;
        __syncthreads();
        sh[tid] += t;
    }
    __syncthreads();
    if (tid == 0) {
        int agg = sh[1023];
        volatile unsigned long long* look = (volatile unsigned long long*)d_look;
        int excl = 0;
        if (b == 0) {
            look[0] = (2ull << 62) | (unsigned)agg;
        } else {
            look[b] = (1ull << 62) | (unsigned)agg;
            int j = b - 1;
            for (;;) {
                unsigned long long w = look[j];
                unsigned long long f = w >> 62;
                if (f == 0) continue;
                excl += (int)(w & 0x3FFFFFFFFFFFFFFFull);
                if (f == 2) break;
                j--;
            }
            look[b] = (2ull << 62) | (unsigned)(excl + agg);
        }
        sh_excl = excl;
    }
    __syncthreads();
    int base = sh_excl;
    d_offs[gid] = base + sh[tid] - v;
    if (gid == NB - 1) d_offs[NB] = base + sh[1023];
}

// 2 points per thread: doubled MLP on the latency-bound atomic path
__global__ void k_scatter(int n) {
    int i0 = (blockIdx.x * blockDim.x + threadIdx.x) * 2;
#pragma unroll
    for (int u = 0; u < 2; u++) {
        int i = i0 + u;
        if (i >= n) return;
        int key = d_keys[i];
        int b = key >> BSHIFT;
        int p = d_offs[b] + atomicSub(&d_cnt[b], 1) - 1;   // restores d_cnt[b] -> 0
        d_bpair[p] = make_int2(key, i);
    }
}

// ---------------- fused rank + probe, sorted-position order (warp-coherent) ----------------

__global__ void __launch_bounds__(256) k_proberank(int n) {
    int p = blockIdx.x * blockDim.x + threadIdx.x;
    if (p >= n) return;
    int2 self = d_bpair[p];
    int key = self.x;
    int b = key >> BSHIFT;

    int s0 = d_offs[b], e0 = d_offs[b + 1];
    int cnt = 0;
    for (int u = s0; u < e0; u++) cnt += (d_bpair[u].x < key);
    int r = s0 + cnt;
    d_rowof[self.y] = r;

    int q[9], s[9], e[9];
#pragma unroll
    for (int g = 0; g < 9; g++) {
        int dq = (g / 3 - 1) * (SGRID * SGRID) + (g % 3 - 1) * SGRID;
        q[g] = key + dq;
        s[g] = d_offs[(q[g] - 1) >> BSHIFT];
        e[g] = d_offs[((q[g] + 1) >> BSHIFT) + 1];
    }

#pragma unroll
    for (int g = 0; g < 9; g++) {
        for (int u = s[g]; u < e[g]; u++) {
            int2 kv = d_bpair[u];
            int d = kv.x - q[g];
            if (d < -1 || d > 1) continue;
            if (d == 0 && g == 4) continue;
            int pos = atomicAdd(&d_mcount, 1);
            if (pos < MAXM) {
                d_mi[pos] = r;
                d_mj[pos] = kv.y;
                d_mk[pos] = g * 3 + d + 1;
            }
        }
    }
}

// ---------------- dense GEMM, ORIGINAL row order: streaming reads, scattered writes ----------------
// out[rowof[i]] = F[i] @ W13.  Tile M=128 x N=64, K=64, fp16 mma.m16n8k16.

#define FHP 72
#define WHP 72

__global__ void __launch_bounds__(128, 5) k_gemm_tc(const float* __restrict__ F,
                                                    float* __restrict__ out, int n) {
    __shared__ __align__(16) __half Ws[64 * WHP];
    __shared__ __align__(16) __half Fs[128 * FHP];
    int tid = threadIdx.x, lane = tid & 31, warp = tid >> 5;

#pragma unroll
    for (int k = 0; k < 8; k++) {
        int x = tid + 128 * k;
        int r = x >> 4, c = x & 15;
        uint2 v = ((const uint2*)d_Wh)[x];
        *(uint2*)&Ws[r * WHP + c * 4] = v;
    }

    // A tile: CONTIGUOUS streaming copy of F rows [row0, row0+128), fp32->fp16 inline
    int row0 = blockIdx.x * 128;
    {
        const float4* src = (const float4*)F;
        int gbase = row0 * 16;               // float4 index of tile start
        int gmax = n * 16;
#pragma unroll
        for (int it = 0; it < 16; it++) {
            int x = it * 128 + tid;          // 0..2047 linear chunk within tile
            int gx = gbase + x;
            float4 v = (gx < gmax) ? src[gx] : make_float4(0.f, 0.f, 0.f, 0.f);
            int r = x >> 4, c4 = x & 15;
            __half2 h0 = __floats2half2_rn(v.x, v.y);
            __half2 h1 = __floats2half2_rn(v.z, v.w);
            *(__half2*)&Fs[r * FHP + c4 * 4] = h0;
            *(__half2*)&Fs[r * FHP + c4 * 4 + 2] = h1;
        }
    }
    __syncthreads();

    int g = lane >> 2, t = lane & 3;
    int mBase = warp * 32;
    float acc[2][8][4];
#pragma unroll
    for (int mt = 0; mt < 2; mt++)
#pragma unroll
        for (int nt = 0; nt < 8; nt++)
#pragma unroll
            for (int u = 0; u < 4; u++) acc[mt][nt][u] = 0.f;

#pragma unroll
    for (int k0 = 0; k0 < 64; k0 += 16) {
        unsigned a[2][4];
#pragma unroll
        for (int mt = 0; mt < 2; mt++) {
            int r = mBase + mt * 16;
            a[mt][0] = *(const unsigned*)&Fs[(r + g) * FHP + k0 + 2 * t];
            a[mt][1] = *(const unsigned*)&Fs[(r + g + 8) * FHP + k0 + 2 * t];
            a[mt][2] = *(const unsigned*)&Fs[(r + g) * FHP + k0 + 2 * t + 8];
            a[mt][3] = *(const unsigned*)&Fs[(r + g + 8) * FHP + k0 + 2 * t + 8];
        }
#pragma unroll
        for (int nt = 0; nt < 8; nt++) {
            unsigned b0 = *(const unsigned*)&Ws[(nt * 8 + g) * WHP + k0 + 2 * t];
            unsigned b1 = *(const unsigned*)&Ws[(nt * 8 + g) * WHP + k0 + 2 * t + 8];
#pragma unroll
            for (int mt = 0; mt < 2; mt++) {
                asm volatile(
                    "mma.sync.aligned.m16n8k16.row.col.f32.f16.f16.f32 "
                    "{%0,%1,%2,%3},{%4,%5,%6,%7},{%8,%9},{%0,%1,%2,%3};"
                    : "+f"(acc[mt][nt][0]), "+f"(acc[mt][nt][1]),
                      "+f"(acc[mt][nt][2]), "+f"(acc[mt][nt][3])
                    : "r"(a[mt][0]), "r"(a[mt][1]), "r"(a[mt][2]), "r"(a[mt][3]),
                      "r"(b0), "r"(b1));
            }
        }
    }

    // epilogue: scatter rows to out[rowof[i]]; 4 threads cover 32B per (row, nt) chunk
#pragma unroll
    for (int mt = 0; mt < 2; mt++) {
        int iA = row0 + mBase + mt * 16 + g;
        int iB = iA + 8;
        int rA = (iA < n) ? d_rowof[iA] : -1;
        int rB = (iB < n) ? d_rowof[iB] : -1;
#pragma unroll
        for (int nt = 0; nt < 8; nt++) {
            int c = nt * 8 + 2 * t;
            if (rA >= 0) *(float2*)&out[(size_t)rA * 64 + c] =
                make_float2(acc[mt][nt][0], acc[mt][nt][1]);
            if (rB >= 0) *(float2*)&out[(size_t)rB * 64 + c] =
                make_float2(acc[mt][nt][2], acc[mt][nt][3]);
        }
    }
}

// ---------------- apply corrections ----------------

__global__ void k_apply(const float* __restrict__ F, const float* __restrict__ W,
                        float* __restrict__ out) {
    int warp = (blockIdx.x * blockDim.x + threadIdx.x) >> 5;
    int lane = threadIdx.x & 31;
    int nwarps = (gridDim.x * blockDim.x) >> 5;
    int total = d_mcount;
    if (total > MAXM) total = MAXM;
    for (int m = warp; m < total; m += nwarps) {
        int r = d_mi[m], j = d_mj[m], k = d_mk[m];
        float fv0 = F[j * 64 + lane];
        float fv1 = F[j * 64 + 32 + lane];
        const float* Wk = W + k * 64 * 64;
        float a0 = 0.f, a1 = 0.f;
#pragma unroll
        for (int ci = 0; ci < 32; ci++) {
            float f = __shfl_sync(0xffffffffu, fv0, ci);
            a0 += f * Wk[ci * 64 + lane];
            a1 += f * Wk[ci * 64 + 32 + lane];
        }
#pragma unroll
        for (int ci = 0; ci < 32; ci++) {
            float f = __shfl_sync(0xffffffffu, fv1, ci);
            a0 += f * Wk[(ci + 32) * 64 + lane];
            a1 += f * Wk[(ci + 32) * 64 + 32 + lane];
        }
        atomicAdd(&out[r * 64 + lane], a0);
        atomicAdd(&out[r * 64 + 32 + lane], a1);
    }
}

// ---------------- launch ----------------

extern "C" void kernel_launch(void* const* d_in, const int* in_sizes, int n_in,
                              void* d_out, int out_size) {
    const float* F = (const float*)d_in[0];
    const float* W = (const float*)d_in[1];
    const int* coords = (const int*)d_in[2];
    int n = in_sizes[2] / 3;
    if (n > MAXN) n = MAXN;
    float* out = (float*)d_out;

    k_keys_hist<<<(n + 255) / 256, 256>>>(coords, W, n);
    k_scan<<<NBLK, 1024>>>();
    k_scatter<<<(n + 511) / 512, 256>>>(n);
    k_proberank<<<(n + 255) / 256, 256>>>(n);
    k_gemm_tc<<<(n + 127) / 128, 128>>>(F, out, n);
    k_apply<<<256, 256>>>(F, W, out);
}